// round 3
// baseline (speedup 1.0000x reference)
#include <cuda_runtime.h>
#include <cuda_bf16.h>

#define MODIFIER_COL 11
#define OWNER_COL    24
#define MAXG         8192
#define F_DIM        128
#define ROWS_PER_THREAD 4

// Persistent scratch (no cudaMalloc allowed). Zero-initialized at load; the
// fused kernel's last block resets everything after consuming it, so each
// graph replay starts clean.
__device__ float g_cnt[MAXG];
__device__ float g_s0[MAXG];
__device__ float g_s1[MAXG];
__device__ unsigned int g_done;

__device__ __forceinline__ void flush_atomic(int g, float c, float s0, float s1)
{
    if (g >= 0 && g < MAXG) {
        atomicAdd(&g_cnt[g], c);
        atomicAdd(&g_s0[g],  s0);
        atomicAdd(&g_s1[g],  s1);
    }
}

// Fused: segmented reduce over sorted keys (4 rows/thread, warp segreduce,
// ~1 atomic per warp-segment) + last-block finalize (2->32->1 MLP) + scratch
// reset. One launch total.
__global__ __launch_bounds__(256) void fused_kernel(
    const float* __restrict__ nf,
    const int*   __restrict__ batch,
    const float* __restrict__ W1,   // [32,2]
    const float* __restrict__ b1,   // [32]
    const float* __restrict__ W2,   // [1,32]
    const float* __restrict__ b2,   // [1]
    float* __restrict__ out,
    int N, int G)
{
    const int lane = threadIdx.x & 31;
    const int tid  = blockIdx.x * blockDim.x + threadIdx.x;
    const int base = tid * ROWS_PER_THREAD;

    // ---- front-batched loads: 1x int4 keys + 8 scattered feature loads ----
    int   k[ROWS_PER_THREAD];
    float a[ROWS_PER_THREAD], b[ROWS_PER_THREAD];

    if (base + ROWS_PER_THREAD <= N) {
        int4 kk = *reinterpret_cast<const int4*>(batch + base);   // 16B aligned
        k[0] = kk.x; k[1] = kk.y; k[2] = kk.z; k[3] = kk.w;
        const float* row = nf + (size_t)base * F_DIM;
        #pragma unroll
        for (int r = 0; r < ROWS_PER_THREAD; ++r) {
            a[r] = __ldg(row + (size_t)r * F_DIM + MODIFIER_COL);
            b[r] = __ldg(row + (size_t)r * F_DIM + OWNER_COL);
        }
    } else {
        #pragma unroll
        for (int r = 0; r < ROWS_PER_THREAD; ++r) {
            int i = base + r;
            if (i < N) {
                k[r] = batch[i];
                a[r] = __ldg(nf + (size_t)i * F_DIM + MODIFIER_COL);
                b[r] = __ldg(nf + (size_t)i * F_DIM + OWNER_COL);
            } else { k[r] = -2; a[r] = 0.f; b[r] = 0.f; }
        }
    }

    // ---- merge the thread's 4 rows into runs; flush interior boundaries ----
    int   key = k[0];
    float c   = (key >= 0) ? 1.f : 0.f;
    float s0  = a[0], s1 = b[0];
    #pragma unroll
    for (int r = 1; r < ROWS_PER_THREAD; ++r) {
        if (k[r] == key) {
            if (k[r] >= 0) { c += 1.f; s0 += a[r]; s1 += b[r]; }
        } else {
            flush_atomic(key, c, s0, s1);   // rare: ~1 per segment boundary
            key = k[r];
            c = (key >= 0) ? 1.f : 0.f;
            s0 = a[r]; s1 = b[r];
        }
    }

    // ---- warp segreduce on trailing partials (keys monotone across lanes) --
    #pragma unroll
    for (int d = 1; d < 32; d <<= 1) {
        int   go = __shfl_down_sync(0xffffffffu, key, d);
        float co = __shfl_down_sync(0xffffffffu, c,   d);
        float x0 = __shfl_down_sync(0xffffffffu, s0,  d);
        float x1 = __shfl_down_sync(0xffffffffu, s1,  d);
        if (lane + d < 32 && go == key) { c += co; s0 += x0; s1 += x1; }
    }
    int  kprev = __shfl_up_sync(0xffffffffu, key, 1);
    if ((lane == 0 || kprev != key))
        flush_atomic(key, c, s0, s1);

    // ---- last-block-done: finalize MLP + reset scratch, all in-kernel ------
    __threadfence();
    __syncthreads();

    __shared__ bool is_last;
    if (threadIdx.x == 0) {
        unsigned int prev = atomicAdd(&g_done, 1u);
        is_last = (prev == gridDim.x - 1);
    }
    __syncthreads();
    if (!is_last) return;

    for (int g = threadIdx.x; g < G; g += blockDim.x) {
        float cc = g_cnt[g];
        float t0 = g_s0[g];
        float t1 = g_s1[g];
        g_cnt[g] = 0.f; g_s0[g] = 0.f; g_s1[g] = 0.f;   // reset for next replay

        float denom = fmaxf(cc, 1.f);
        float f0 = 1.f - t0 / denom;
        float f1 = 1.f - t1 / denom;

        float acc = __ldg(b2);
        #pragma unroll
        for (int j = 0; j < 32; ++j) {
            float h = fmaf(f0, __ldg(W1 + 2 * j),
                      fmaf(f1, __ldg(W1 + 2 * j + 1), __ldg(b1 + j)));
            h   = fmaxf(h, 0.f);
            acc = fmaf(__ldg(W2 + j), h, acc);
        }
        float score = 1.f / (1.f + __expf(-acc));
        out[g] = (cc > 0.f) ? score : 0.f;
    }
    if (threadIdx.x == 0) g_done = 0u;   // reset counter for next replay
}

extern "C" void kernel_launch(void* const* d_in, const int* in_sizes, int n_in,
                              void* d_out, int out_size)
{
    // order: node_features, batch, graph_embedding, W1, b1, W2, b2
    const float* nf    = (const float*)d_in[0];
    const int*   batch = (const int*)d_in[1];
    const float* W1    = (const float*)d_in[3];
    const float* b1    = (const float*)d_in[4];
    const float* W2    = (const float*)d_in[5];
    const float* b2    = (const float*)d_in[6];
    float*       out   = (float*)d_out;

    int N = in_sizes[1];
    int G = in_sizes[2] / F_DIM;
    if (G <= 0 || G > MAXG) G = out_size;

    int threads = 256;
    int rows_per_block = threads * ROWS_PER_THREAD;
    int blocks = (N + rows_per_block - 1) / rows_per_block;

    fused_kernel<<<blocks, threads>>>(nf, batch, W1, b1, W2, b2, out, N, G);
}